// round 1
// baseline (speedup 1.0000x reference)
#include <cuda_runtime.h>
#include <math.h>

#define VOL   2097152              // 128^3
#define NB    4
#define S2D   16384                // 128*128 (z stride)

// Normalized 1-D Gaussian weights (sigma=1.6, 7 taps), sum = 1.
#define W0 0.25603832f   // center
#define W1 0.21061137f   // +-1
#define W2 0.11722290f   // +-2
#define W3 0.04414655f   // +-3

// Scratch (allocation-free contract: __device__ globals)
__device__ float g_vn[(size_t)NB * VOL];   // |curl(v)|
__device__ float g_a [(size_t)NB * VOL];   // d   smoothed in x,y
__device__ float g_b [(size_t)NB * VOL];   // vn  smoothed in x,y

// ---------------------------------------------------------------------------
// Kernel 1: vorticity magnitude.  fdiff(f,i) = f[min(i,126)+1]-f[min(i,126)]
// ---------------------------------------------------------------------------
__global__ __launch_bounds__(256)
void curl_norm_kernel(const float* __restrict__ v) {
    int idx = blockIdx.x * 256 + threadIdx.x;          // 0 .. 4*VOL-1
    int n = idx >> 21;                                  // /VOL
    int o = idx & (VOL - 1);
    int z = o >> 14;
    int y = (o >> 7) & 127;
    int x = o & 127;

    const float* pu = v + (size_t)(n * 3 + 0) * VOL;
    const float* pv = v + (size_t)(n * 3 + 1) * VOL;
    const float* pw = v + (size_t)(n * 3 + 2) * VOL;

    int zz = min(z, 126), yy = min(y, 126), xx = min(x, 126);
    int oz = zz * S2D + y * 128 + x;
    int oy = z * S2D + yy * 128 + x;
    int ox = z * S2D + y * 128 + xx;

    float du_dz = pu[oz + S2D] - pu[oz];
    float du_dy = pu[oy + 128] - pu[oy];
    float dv_dz = pv[oz + S2D] - pv[oz];
    float dv_dx = pv[ox + 1]   - pv[ox];
    float dw_dy = pw[oy + 128] - pw[oy];
    float dw_dx = pw[ox + 1]   - pw[ox];

    float cu = dw_dy - dv_dz;
    float cv = du_dz - dw_dx;
    float cw = dv_dx - du_dy;

    g_vn[(size_t)n * VOL + o] = sqrtf(cu * cu + cv * cv + cw * cw);
}

// ---------------------------------------------------------------------------
// Kernel 2: separable X+Y Gaussian smoothing of one (n,z) slice, tiled.
// sel==0: src = external d, dst = g_a ; sel==1: src = g_vn, dst = g_b
// Zero padding outside the 128x128 slice (matches conv zero-pad).
// ---------------------------------------------------------------------------
#define TS 32
#define LD 38   // TS + 2*3

__global__ __launch_bounds__(256)
void smooth_xy_kernel(const float* __restrict__ ext_src, int sel) {
    const float* src = (sel == 0) ? ext_src : g_vn;
    float*       dst = (sel == 0) ? g_a    : g_b;

    int nz = blockIdx.z;             // n*128 + z
    int n = nz >> 7, z = nz & 127;
    int tx0 = blockIdx.x * TS;
    int ty0 = blockIdx.y * TS;
    const float* slice = src + (size_t)n * VOL + z * S2D;

    __shared__ float s_in[LD][LD];
    __shared__ float s_tmp[LD][TS];

    int tid = threadIdx.x;

    for (int l = tid; l < LD * LD; l += 256) {
        int ly = l / LD, lx = l - ly * LD;
        int gy = ty0 + ly - 3, gx = tx0 + lx - 3;
        float val = 0.f;
        if ((unsigned)gy < 128u && (unsigned)gx < 128u)
            val = slice[gy * 128 + gx];
        s_in[ly][lx] = val;
    }
    __syncthreads();

    for (int l = tid; l < LD * TS; l += 256) {
        int ly = l >> 5, ox = l & 31;
        const float* r = &s_in[ly][ox];
        s_tmp[ly][ox] = W0 * r[3]
                      + W1 * (r[2] + r[4])
                      + W2 * (r[1] + r[5])
                      + W3 * (r[0] + r[6]);
    }
    __syncthreads();

    float* out_slice = dst + (size_t)n * VOL + z * S2D;
    for (int l = tid; l < TS * TS; l += 256) {
        int oy = l >> 5, ox = l & 31;
        float acc = W0 * s_tmp[oy + 3][ox]
                  + W1 * (s_tmp[oy + 2][ox] + s_tmp[oy + 4][ox])
                  + W2 * (s_tmp[oy + 1][ox] + s_tmp[oy + 5][ox])
                  + W3 * (s_tmp[oy + 0][ox] + s_tmp[oy + 6][ox]);
        out_slice[(ty0 + oy) * 128 + tx0 + ox] = acc;
    }
}

// ---------------------------------------------------------------------------
// Kernel 3: fused Z-smooth (rolling 7-tap window) + flip + cumsum + transform
// + trapezoid integration + clip.  One thread per (n,y,x) column.
// Walks z from 127 down to 0 (== flipped index zf from 0..127).
// ---------------------------------------------------------------------------
__global__ __launch_bounds__(256)
void integrate_kernel(float* __restrict__ out) {
    int t = blockIdx.x * 256 + threadIdx.x;   // 0..65535
    int n = t >> 14;
    int yx = t & 16383;

    const float* A = g_a + (size_t)n * VOL + yx;  // ds (xy-smoothed)
    const float* B = g_b + (size_t)n * VOL + yx;  // vn (xy-smoothed)

    // rolling window: a[k] = f(z + k - 3), zero-padded outside [0,127]
    float a[7], b[7];
#pragma unroll
    for (int k = 0; k < 7; k++) { a[k] = 0.f; b[k] = 0.f; }
#pragma unroll
    for (int k = 0; k < 4; k++) {
        a[k] = A[(124 + k) * S2D];
        b[k] = B[(124 + k) * S2D];
    }

    float xacc = 0.f, iv = 0.f, tprev = 0.f, vprev = 0.f;

#pragma unroll 4
    for (int zf = 0; zf < 128; ++zf) {
        int z = 127 - zf;
        // prefetch the element entering the window at next step: f(z-4)
        float na = 0.f, nb = 0.f;
        int pz = z - 4;
        if (pz >= 0) { na = A[pz * S2D]; nb = B[pz * S2D]; }

        float ds_s = W0 * a[3] + W1 * (a[2] + a[4])
                   + W2 * (a[1] + a[5]) + W3 * (a[0] + a[6]);
        float vn_s = W0 * b[3] + W1 * (b[2] + b[4])
                   + W2 * (b[1] + b[5]) + W3 * (b[0] + b[6]);

        xacc += ds_s;                               // cumsum of flipped ds, DX=1
        float tt = (xacc * 20.f + 1.f) * expf(-20.f * xacc);

        if (zf == 0) {
            iv = (1.f - tt) * vn_s;                 // front term
        } else {
            iv += (tprev - tt) * (vprev + vn_s) * 0.5f;  // trapezoid
        }
        tprev = tt; vprev = vn_s;

#pragma unroll
        for (int k = 6; k >= 1; k--) { a[k] = a[k - 1]; b[k] = b[k - 1]; }
        a[0] = na; b[0] = nb;
    }

    out[t] = fminf(fmaxf(iv, 0.f), 1.f);
}

// ---------------------------------------------------------------------------
extern "C" void kernel_launch(void* const* d_in, const int* in_sizes, int n_in,
                              void* d_out, int out_size) {
    const float* d = (const float*)d_in[0];
    const float* v = (const float*)d_in[1];
    if (in_sizes[0] > in_sizes[1]) {   // safety: d is the smaller tensor
        const float* tmp = d; d = v; v = tmp;
    }
    float* out = (float*)d_out;

    curl_norm_kernel<<<(NB * VOL) / 256, 256>>>(v);

    dim3 g2(128 / TS, 128 / TS, NB * 128);
    smooth_xy_kernel<<<g2, 256>>>(d, 0);        // d  -> g_a
    smooth_xy_kernel<<<g2, 256>>>(nullptr, 1);  // vn -> g_b

    integrate_kernel<<<65536 / 256, 256>>>(out);
}

// round 2
// speedup vs baseline: 1.0830x; 1.0830x over previous
#include <cuda_runtime.h>
#include <math.h>

#define VOL   2097152              // 128^3
#define NB    4
#define S2D   16384                // 128*128 (z stride)

// Normalized 1-D Gaussian weights (sigma=1.6, 7 taps), sum = 1.
#define W0 0.25603832f   // center
#define W1 0.21061137f   // +-1
#define W2 0.11722290f   // +-2
#define W3 0.04414655f   // +-3

// Scratch (allocation-free contract: __device__ globals)
__device__ float g_a [(size_t)NB * VOL];   // d   smoothed in x,y
__device__ float g_b [(size_t)NB * VOL];   // |curl v| smoothed in x,y

#define TS 32
#define LD 38   // TS + 2*3

// ---------------------------------------------------------------------------
// Kernel 1: FUSED |curl(v)| + separable X,Y Gaussian smoothing -> g_b.
// One block per (n, z, 32x32 tile). The 38x38 halo tile of vn is computed
// on the fly from v (12 clamped loads per point, L1/L2 absorb reuse).
// fdiff(f,i) = f[min(i,126)+1]-f[min(i,126)]; conv uses zero padding.
// ---------------------------------------------------------------------------
__global__ __launch_bounds__(256)
void curl_smooth_xy_kernel(const float* __restrict__ v) {
    int nz = blockIdx.z;             // n*128 + z
    int n = nz >> 7, z = nz & 127;
    int tx0 = blockIdx.x * TS;
    int ty0 = blockIdx.y * TS;

    const float* pu = v + (size_t)(n * 3 + 0) * VOL;
    const float* pv = v + (size_t)(n * 3 + 1) * VOL;
    const float* pw = v + (size_t)(n * 3 + 2) * VOL;

    __shared__ float s_in[LD][LD];
    __shared__ float s_tmp[LD][TS];

    int tid = threadIdx.x;
    int zz = min(z, 126);

    for (int l = tid; l < LD * LD; l += 256) {
        int ly = l / LD, lx = l - ly * LD;
        int gy = ty0 + ly - 3, gx = tx0 + lx - 3;
        float val = 0.f;
        if ((unsigned)gy < 128u && (unsigned)gx < 128u) {
            int yy = min(gy, 126), xx = min(gx, 126);
            int oz = zz * S2D + gy * 128 + gx;
            int oy = z  * S2D + yy * 128 + gx;
            int ox = z  * S2D + gy * 128 + xx;

            float du_dz = pu[oz + S2D] - pu[oz];
            float du_dy = pu[oy + 128] - pu[oy];
            float dv_dz = pv[oz + S2D] - pv[oz];
            float dv_dx = pv[ox + 1]   - pv[ox];
            float dw_dy = pw[oy + 128] - pw[oy];
            float dw_dx = pw[ox + 1]   - pw[ox];

            float cu = dw_dy - dv_dz;
            float cv = du_dz - dw_dx;
            float cw = dv_dx - du_dy;
            val = sqrtf(cu * cu + cv * cv + cw * cw);
        }
        s_in[ly][lx] = val;
    }
    __syncthreads();

    for (int l = tid; l < LD * TS; l += 256) {
        int ly = l >> 5, ox = l & 31;
        const float* r = &s_in[ly][ox];
        s_tmp[ly][ox] = W0 * r[3]
                      + W1 * (r[2] + r[4])
                      + W2 * (r[1] + r[5])
                      + W3 * (r[0] + r[6]);
    }
    __syncthreads();

    float* out_slice = g_b + (size_t)n * VOL + z * S2D;
    for (int l = tid; l < TS * TS; l += 256) {
        int oy = l >> 5, ox = l & 31;
        float acc = W0 * s_tmp[oy + 3][ox]
                  + W1 * (s_tmp[oy + 2][ox] + s_tmp[oy + 4][ox])
                  + W2 * (s_tmp[oy + 1][ox] + s_tmp[oy + 5][ox])
                  + W3 * (s_tmp[oy + 0][ox] + s_tmp[oy + 6][ox]);
        out_slice[(ty0 + oy) * 128 + tx0 + ox] = acc;
    }
}

// ---------------------------------------------------------------------------
// Kernel 2: separable X+Y Gaussian smoothing of d -> g_a (zero-padded).
// ---------------------------------------------------------------------------
__global__ __launch_bounds__(256)
void smooth_xy_kernel(const float* __restrict__ src) {
    int nz = blockIdx.z;
    int n = nz >> 7, z = nz & 127;
    int tx0 = blockIdx.x * TS;
    int ty0 = blockIdx.y * TS;
    const float* slice = src + (size_t)n * VOL + z * S2D;

    __shared__ float s_in[LD][LD];
    __shared__ float s_tmp[LD][TS];

    int tid = threadIdx.x;

    for (int l = tid; l < LD * LD; l += 256) {
        int ly = l / LD, lx = l - ly * LD;
        int gy = ty0 + ly - 3, gx = tx0 + lx - 3;
        float val = 0.f;
        if ((unsigned)gy < 128u && (unsigned)gx < 128u)
            val = slice[gy * 128 + gx];
        s_in[ly][lx] = val;
    }
    __syncthreads();

    for (int l = tid; l < LD * TS; l += 256) {
        int ly = l >> 5, ox = l & 31;
        const float* r = &s_in[ly][ox];
        s_tmp[ly][ox] = W0 * r[3]
                      + W1 * (r[2] + r[4])
                      + W2 * (r[1] + r[5])
                      + W3 * (r[0] + r[6]);
    }
    __syncthreads();

    float* out_slice = g_a + (size_t)n * VOL + z * S2D;
    for (int l = tid; l < TS * TS; l += 256) {
        int oy = l >> 5, ox = l & 31;
        float acc = W0 * s_tmp[oy + 3][ox]
                  + W1 * (s_tmp[oy + 2][ox] + s_tmp[oy + 4][ox])
                  + W2 * (s_tmp[oy + 1][ox] + s_tmp[oy + 5][ox])
                  + W3 * (s_tmp[oy + 0][ox] + s_tmp[oy + 6][ox]);
        out_slice[(ty0 + oy) * 128 + tx0 + ox] = acc;
    }
}

// ---------------------------------------------------------------------------
// Kernel 3: fused Z-smooth + flip + cumsum + transform + trapezoid + clip.
// 4 threads per column (chunks of 32 zf-steps each); segmented shfl scan
// provides the cumsum offset; boundary (tprev, vprev) reconstructed
// analytically; shfl_xor reduction of the 4 partial integrals.
// Lane layout: col = t>>2, chunk = t&3  (4 consecutive lanes per column).
// ---------------------------------------------------------------------------
__global__ __launch_bounds__(256)
void integrate_kernel(float* __restrict__ out) {
    int t = blockIdx.x * 256 + threadIdx.x;   // 0..262143
    int chunk = t & 3;
    int colg  = t >> 2;                        // 0..65535
    int n  = colg >> 14;
    int yx = colg & 16383;

    const float* A = g_a + (size_t)n * VOL + yx;  // ds  (xy-smoothed)
    const float* B = g_b + (size_t)n * VOL + yx;  // vn  (xy-smoothed)

    const int z0 = 127 - 32 * chunk;           // first z of this chunk (walk down)

    // ---------------- Pass 1: local sum of z-smoothed ds over 32 steps ----
    float a[7];
#pragma unroll
    for (int k = 0; k < 7; k++) {
        int zi = z0 + k - 3;
        a[k] = ((unsigned)zi < 128u) ? A[zi * S2D] : 0.f;
    }
    float S = 0.f;
    {
        int z = z0;
#pragma unroll 8
        for (int i = 0; i < 32; i++) {
            float na = 0.f;
            int pz = z - 4;
            if (pz >= 0) na = A[pz * S2D];
            S += W0 * a[3] + W1 * (a[2] + a[4])
               + W2 * (a[1] + a[5]) + W3 * (a[0] + a[6]);
#pragma unroll
            for (int k = 6; k >= 1; k--) a[k] = a[k - 1];
            a[0] = na;
            z--;
        }
    }

    // Segmented (width-4) inclusive scan -> exclusive offset
    float incl = S;
    float u1 = __shfl_up_sync(0xffffffffu, incl, 1);
    if (chunk >= 1) incl += u1;
    float u2 = __shfl_up_sync(0xffffffffu, incl, 2);
    if (chunk >= 2) incl += u2;
    float Xoff = incl - S;

    // ---------------- Boundary state for chunk > 0 ------------------------
    float tprev = 0.f, vprev = 0.f;
    if (chunk > 0) {
        int zb = z0 + 1;   // z of zf = 32*chunk - 1; taps all in-bounds here
        vprev = W0 * B[zb * S2D]
              + W1 * (B[(zb - 1) * S2D] + B[(zb + 1) * S2D])
              + W2 * (B[(zb - 2) * S2D] + B[(zb + 2) * S2D])
              + W3 * (B[(zb - 3) * S2D] + B[(zb + 3) * S2D]);
        tprev = (Xoff * 20.f + 1.f) * __expf(-20.f * Xoff);
    }

    // ---------------- Pass 2: full evaluation -----------------------------
    float b[7];
#pragma unroll
    for (int k = 0; k < 7; k++) {
        int zi = z0 + k - 3;
        if ((unsigned)zi < 128u) {
            a[k] = A[zi * S2D];
            b[k] = B[zi * S2D];
        } else {
            a[k] = 0.f; b[k] = 0.f;
        }
    }

    float xacc = Xoff, iv = 0.f;
    int z = z0;
#pragma unroll 8
    for (int i = 0; i < 32; i++) {
        float na = 0.f, nb = 0.f;
        int pz = z - 4;
        if (pz >= 0) { na = A[pz * S2D]; nb = B[pz * S2D]; }

        float ds_s = W0 * a[3] + W1 * (a[2] + a[4])
                   + W2 * (a[1] + a[5]) + W3 * (a[0] + a[6]);
        float vn_s = W0 * b[3] + W1 * (b[2] + b[4])
                   + W2 * (b[1] + b[5]) + W3 * (b[0] + b[6]);

        xacc += ds_s;
        float tt = (xacc * 20.f + 1.f) * __expf(-20.f * xacc);

        if (i == 0 && chunk == 0)
            iv = (1.f - tt) * vn_s;                       // front term
        else
            iv += (tprev - tt) * (vprev + vn_s) * 0.5f;   // trapezoid
        tprev = tt; vprev = vn_s;

#pragma unroll
        for (int k = 6; k >= 1; k--) { a[k] = a[k - 1]; b[k] = b[k - 1]; }
        a[0] = na; b[0] = nb;
        z--;
    }

    // Reduce the 4 chunk partials within each 4-lane group
    iv += __shfl_xor_sync(0xffffffffu, iv, 1);
    iv += __shfl_xor_sync(0xffffffffu, iv, 2);

    if (chunk == 0)
        out[colg] = fminf(fmaxf(iv, 0.f), 1.f);
}

// ---------------------------------------------------------------------------
extern "C" void kernel_launch(void* const* d_in, const int* in_sizes, int n_in,
                              void* d_out, int out_size) {
    const float* d = (const float*)d_in[0];
    const float* v = (const float*)d_in[1];
    if (in_sizes[0] > in_sizes[1]) {   // safety: d is the smaller tensor
        const float* tmp = d; d = v; v = tmp;
    }
    float* out = (float*)d_out;

    dim3 g2(128 / TS, 128 / TS, NB * 128);
    curl_smooth_xy_kernel<<<g2, 256>>>(v);   // |curl v| -> smooth xy -> g_b
    smooth_xy_kernel<<<g2, 256>>>(d);        // d -> smooth xy -> g_a

    integrate_kernel<<<262144 / 256, 256>>>(out);
}